// round 2
// baseline (speedup 1.0000x reference)
#include <cuda_runtime.h>

#define NN   50000
#define NE   1600000
#define DIN  2000
#define H1   500
#define H2   128
#define DD   64

// ---------------- scratch (static device globals; no allocation) ----------------
static __device__ float g_z1[2 * NN * H1];     // 200 MB
static __device__ float g_z2[2 * NN * H2];     // 51 MB
static __device__ float g_feat[NN * DD];
static __device__ float g_xw[NN * DD];
static __device__ float g_agg[NN * DD];
static __device__ float g_y1[NN * DD];
static __device__ float g_y2[NN * 32];
static __device__ float g_cs[NN];
static __device__ float g_cd[NN];
static __device__ float g_alpha1[2 * H1], g_beta1[2 * H1];
static __device__ float g_alpha2[2 * H2], g_beta2[2 * H2];
static __device__ float g_betad[2 * DD];

// ---------------- small prep: fold BN into GEMM epilogue vectors ----------------
__global__ void prep_kernel(const float* __restrict__ b1, const float* __restrict__ g1,
                            const float* __restrict__ be1, const float* __restrict__ m1,
                            const float* __restrict__ v1,
                            const float* __restrict__ b2, const float* __restrict__ g2,
                            const float* __restrict__ be2, const float* __restrict__ m2,
                            const float* __restrict__ v2,
                            const float* __restrict__ bd)
{
    int t = threadIdx.x;
    for (int i = t; i < 2 * H1; i += blockDim.x) {
        float a = g1[i] * rsqrtf(v1[i] + 1e-5f);
        g_alpha1[i] = a;
        g_beta1[i]  = (b1[i] - m1[i]) * a + be1[i];
    }
    for (int i = t; i < 2 * H2; i += blockDim.x) {
        float a = g2[i] * rsqrtf(v2[i] + 1e-5f);
        g_alpha2[i] = a;
        g_beta2[i]  = (b2[i] - m2[i]) * a + be2[i];
    }
    for (int i = t; i < 2 * DD; i += blockDim.x)
        g_betad[i] = 0.5f * bd[i];
}

// ---------------- zero helper ----------------
__global__ void zero_kernel(float* __restrict__ p, int n)
{
    int i = blockIdx.x * blockDim.x + threadIdx.x;
    if (i < n) p[i] = 0.0f;
}

// ---------------- degrees ----------------
__global__ void deg_count_kernel(const int* __restrict__ src, const int* __restrict__ dst)
{
    int i = blockIdx.x * blockDim.x + threadIdx.x;
    if (i < NE) {
        atomicAdd(&g_cs[src[i]], 1.0f);
        atomicAdd(&g_cd[dst[i]], 1.0f);
    }
}

__global__ void deg_finish_kernel()
{
    int i = blockIdx.x * blockDim.x + threadIdx.x;
    if (i < NN) {
        g_cs[i] = rsqrtf(fmaxf(g_cs[i], 1.0f));
        g_cd[i] = rsqrtf(fmaxf(g_cd[i], 1.0f));
    }
}

// ---------------- generic 64x64x16 SIMT GEMM with fused epilogue ----------------
// C[row,col] = epi( acc * rowScale[row] * (colScale ? colScale[col] : scalarAlpha)
//                   + colBias[col] (+ C if accumulate) ), optional relu.
__global__ __launch_bounds__(256)
void gemm64_kernel(const float* __restrict__ A, const float* __restrict__ B,
                   float* __restrict__ C, int M, int K, int Nc,
                   const float* __restrict__ colScale, const float* __restrict__ colBias,
                   const float* __restrict__ rowScale, float scalarAlpha,
                   int accumulate, int relu)
{
    __shared__ float As[16][64];   // As[k][m]
    __shared__ float Bs[16][64];   // Bs[k][n]

    const int t  = threadIdx.x;
    const int bm = blockIdx.y * 64;
    const int bn = blockIdx.x * 64;

    const int a_row = t >> 2;          // 0..63
    const int a_col = (t & 3) * 4;     // 0,4,8,12
    const int b_row = t >> 4;          // 0..15
    const int b_col = (t & 15) * 4;    // 0..60

    const int tx = t & 15;             // n micro-tile
    const int ty = t >> 4;             // m micro-tile

    float acc[4][4];
#pragma unroll
    for (int i = 0; i < 4; i++)
#pragma unroll
        for (int j = 0; j < 4; j++) acc[i][j] = 0.0f;

    for (int k0 = 0; k0 < K; k0 += 16) {
        // --- load A tile (transposed into smem) ---
        float4 av = make_float4(0.f, 0.f, 0.f, 0.f);
        int ar = bm + a_row;
        if (ar < M) {
            if (k0 + a_col + 3 < K) {
                av = *(const float4*)(A + (size_t)ar * K + k0 + a_col);
            } else {
                float tmp[4] = {0.f, 0.f, 0.f, 0.f};
#pragma unroll
                for (int i = 0; i < 4; i++) {
                    int kk = k0 + a_col + i;
                    if (kk < K) tmp[i] = A[(size_t)ar * K + kk];
                }
                av = make_float4(tmp[0], tmp[1], tmp[2], tmp[3]);
            }
        }
        As[a_col + 0][a_row] = av.x;
        As[a_col + 1][a_row] = av.y;
        As[a_col + 2][a_row] = av.z;
        As[a_col + 3][a_row] = av.w;

        // --- load B tile ---
        float4 bv = make_float4(0.f, 0.f, 0.f, 0.f);
        int br = k0 + b_row;
        int bc = bn + b_col;
        if (br < K) {
            if (bc + 3 < Nc) {
                bv = *(const float4*)(B + (size_t)br * Nc + bc);
            } else {
                float tmp[4] = {0.f, 0.f, 0.f, 0.f};
#pragma unroll
                for (int i = 0; i < 4; i++) {
                    int cc = bc + i;
                    if (cc < Nc) tmp[i] = B[(size_t)br * Nc + cc];
                }
                bv = make_float4(tmp[0], tmp[1], tmp[2], tmp[3]);
            }
        }
        *(float4*)&Bs[b_row][b_col] = bv;

        __syncthreads();

#pragma unroll
        for (int k = 0; k < 16; k++) {
            float4 a = *(const float4*)&As[k][ty * 4];
            float4 b = *(const float4*)&Bs[k][tx * 4];
            acc[0][0] += a.x * b.x; acc[0][1] += a.x * b.y; acc[0][2] += a.x * b.z; acc[0][3] += a.x * b.w;
            acc[1][0] += a.y * b.x; acc[1][1] += a.y * b.y; acc[1][2] += a.y * b.z; acc[1][3] += a.y * b.w;
            acc[2][0] += a.z * b.x; acc[2][1] += a.z * b.y; acc[2][2] += a.z * b.z; acc[2][3] += a.z * b.w;
            acc[3][0] += a.w * b.x; acc[3][1] += a.w * b.y; acc[3][2] += a.w * b.z; acc[3][3] += a.w * b.w;
        }
        __syncthreads();
    }

    // --- epilogue ---
#pragma unroll
    for (int i = 0; i < 4; i++) {
        int row = bm + ty * 4 + i;
        if (row >= M) continue;
        float rs = rowScale ? rowScale[row] : 1.0f;
#pragma unroll
        for (int j = 0; j < 4; j++) {
            int col = bn + tx * 4 + j;
            if (col >= Nc) continue;
            float cs = colScale ? colScale[col] : scalarAlpha;
            float v = acc[i][j] * rs * cs;
            if (colBias) v += colBias[col];
            size_t idx = (size_t)row * Nc + col;
            if (accumulate) v += C[idx];
            if (relu) v = fmaxf(v, 0.0f);
            C[idx] = v;
        }
    }
}

// ---------------- edge scatter: agg[dst] += xw[src] (float4 chunks) ----------------
__global__ void scatter_kernel(const float* __restrict__ xw, float* __restrict__ agg,
                               const int* __restrict__ src, const int* __restrict__ dst,
                               int dout4)
{
    int idx = blockIdx.x * blockDim.x + threadIdx.x;
    int total = NE * dout4;
    if (idx >= total) return;
    int e = idx / dout4;
    int c = (idx - e * dout4) * 4;
    int dout = dout4 * 4;
    int s = src[e], d = dst[e];
    float4 v = *(const float4*)(xw + (size_t)s * dout + c);
    float* p = agg + (size_t)d * dout + c;
    atomicAdd(p + 0, v.x);
    atomicAdd(p + 1, v.y);
    atomicAdd(p + 2, v.z);
    atomicAdd(p + 3, v.w);
}

// ---------------- finalize: out = [relu]( agg * cd[row] + bias ) ----------------
__global__ void finalize_kernel(const float* __restrict__ agg, float* __restrict__ out,
                                const float* __restrict__ bias, int dout, int relu)
{
    int idx = blockIdx.x * blockDim.x + threadIdx.x;
    if (idx >= NN * dout) return;
    int n = idx / dout;
    int c = idx - n * dout;
    float v = agg[idx] * g_cd[n] + bias[c];
    if (relu) v = fmaxf(v, 0.0f);
    out[idx] = v;
}

// ---------------- launch ----------------
static inline dim3 gemm_grid(int M, int Nc)
{
    return dim3((Nc + 63) / 64, (M + 63) / 64);
}

extern "C" void kernel_launch(void* const* d_in, const int* in_sizes, int n_in,
                              void* d_out, int out_size)
{
    const float* h   = (const float*)d_in[0];
    const int*   src = (const int*)  d_in[1];
    const int*   dst = (const int*)  d_in[2];
    const float* W1  = (const float*)d_in[3];
    const float* b1  = (const float*)d_in[4];
    const float* g1  = (const float*)d_in[5];
    const float* be1 = (const float*)d_in[6];
    const float* m1  = (const float*)d_in[7];
    const float* v1  = (const float*)d_in[8];
    const float* W2  = (const float*)d_in[9];
    const float* b2  = (const float*)d_in[10];
    const float* g2  = (const float*)d_in[11];
    const float* be2 = (const float*)d_in[12];
    const float* m2  = (const float*)d_in[13];
    const float* v2  = (const float*)d_in[14];
    const float* Wd  = (const float*)d_in[15];
    const float* bd  = (const float*)d_in[16];
    const float* Wg0 = (const float*)d_in[17];
    const float* bg0 = (const float*)d_in[18];
    const float* Wg1 = (const float*)d_in[19];
    const float* bg1 = (const float*)d_in[20];
    const float* Wg2 = (const float*)d_in[21];
    const float* bg2 = (const float*)d_in[22];
    float* out = (float*)d_out;

    // device addresses of scratch globals
    float *z1, *z2, *feat, *xw, *agg, *y1, *y2, *cs, *cd;
    float *alpha1, *beta1, *alpha2, *beta2, *betad;
    cudaGetSymbolAddress((void**)&z1, g_z1);
    cudaGetSymbolAddress((void**)&z2, g_z2);
    cudaGetSymbolAddress((void**)&feat, g_feat);
    cudaGetSymbolAddress((void**)&xw, g_xw);
    cudaGetSymbolAddress((void**)&agg, g_agg);
    cudaGetSymbolAddress((void**)&y1, g_y1);
    cudaGetSymbolAddress((void**)&y2, g_y2);
    cudaGetSymbolAddress((void**)&cs, g_cs);
    cudaGetSymbolAddress((void**)&cd, g_cd);
    cudaGetSymbolAddress((void**)&alpha1, g_alpha1);
    cudaGetSymbolAddress((void**)&beta1, g_beta1);
    cudaGetSymbolAddress((void**)&alpha2, g_alpha2);
    cudaGetSymbolAddress((void**)&beta2, g_beta2);
    cudaGetSymbolAddress((void**)&betad, g_betad);

    // BN folding vectors
    prep_kernel<<<1, 512>>>(b1, g1, be1, m1, v1, b2, g2, be2, m2, v2, bd);

    // degrees
    zero_kernel<<<(NN + 255) / 256, 256>>>(cs, NN);
    zero_kernel<<<(NN + 255) / 256, 256>>>(cd, NN);
    deg_count_kernel<<<(NE + 255) / 256, 256>>>(src, dst);
    deg_finish_kernel<<<(NN + 255) / 256, 256>>>();

    // encoder layer 1: z1[m] = BN1(h[m] @ W1[m] + b1[m])   (folded: acc*alpha1 + beta1)
    for (int m = 0; m < 2; m++) {
        gemm64_kernel<<<gemm_grid(NN, H1), 256>>>(
            h + (size_t)m * NN * DIN, W1 + (size_t)m * DIN * H1,
            z1 + (size_t)m * NN * H1, NN, DIN, H1,
            alpha1 + m * H1, beta1 + m * H1, nullptr, 1.0f, 0, 0);
    }

    // encoder layer 2: z2[m] = BN2(z1[m] @ W2[m] + b2[m])
    for (int m = 0; m < 2; m++) {
        gemm64_kernel<<<gemm_grid(NN, H2), 256>>>(
            z1 + (size_t)m * NN * H1, W2 + (size_t)m * H1 * H2,
            z2 + (size_t)m * NN * H2, NN, H1, H2,
            alpha2 + m * H2, beta2 + m * H2, nullptr, 1.0f, 0, 0);
    }

    // decoder + modality mean: feat = 0.5*sum_m (z2[m] @ Wd[m] + bd[m])
    gemm64_kernel<<<gemm_grid(NN, DD), 256>>>(
        z2, Wd, feat, NN, H2, DD,
        nullptr, betad, nullptr, 0.5f, 0, 0);
    gemm64_kernel<<<gemm_grid(NN, DD), 256>>>(
        z2 + (size_t)NN * H2, Wd + (size_t)H2 * DD, feat, NN, H2, DD,
        nullptr, betad + DD, nullptr, 0.5f, 1, 0);

    // ---- GraphConv 1: 64 -> 64, relu ----
    zero_kernel<<<(NN * DD + 255) / 256, 256>>>(agg, NN * DD);
    gemm64_kernel<<<gemm_grid(NN, DD), 256>>>(
        feat, Wg0, xw, NN, DD, DD, nullptr, nullptr, cs, 1.0f, 0, 0);
    scatter_kernel<<<(NE * 16 + 255) / 256, 256>>>(xw, agg, src, dst, 16);
    finalize_kernel<<<(NN * DD + 255) / 256, 256>>>(agg, y1, bg0, DD, 1);

    // ---- GraphConv 2: 64 -> 32, relu ----
    zero_kernel<<<(NN * 32 + 255) / 256, 256>>>(agg, NN * 32);
    gemm64_kernel<<<gemm_grid(NN, 32), 256>>>(
        y1, Wg1, xw, NN, DD, 32, nullptr, nullptr, cs, 1.0f, 0, 0);
    scatter_kernel<<<(NE * 8 + 255) / 256, 256>>>(xw, agg, src, dst, 8);
    finalize_kernel<<<(NN * 32 + 255) / 256, 256>>>(agg, y2, bg1, 32, 1);

    // ---- GraphConv 3: 32 -> 4, no relu, write output ----
    zero_kernel<<<(NN * 4 + 255) / 256, 256>>>(agg, NN * 4);
    gemm64_kernel<<<gemm_grid(NN, 4), 256>>>(
        y2, Wg2, xw, NN, 32, 4, nullptr, nullptr, cs, 1.0f, 0, 0);
    scatter_kernel<<<(NE * 1 + 255) / 256, 256>>>(xw, agg, src, dst, 1);
    finalize_kernel<<<(NN * 4 + 255) / 256, 256>>>(agg, out, bg2, 4, 0);
}

// round 3
// speedup vs baseline: 2.4071x; 2.4071x over previous
#include <cuda_runtime.h>

#define NN   50000
#define NE   1600000
#define DIN  2000
#define H1   500
#define H2   128
#define DD   64

// ---------------- scratch (static device globals; no allocation) ----------------
static __device__ float g_z1[2 * NN * H1];     // 200 MB
static __device__ float g_z2[2 * NN * H2];     // 51 MB
static __device__ float g_feat[NN * DD];
static __device__ float g_xw[NN * DD];
static __device__ float g_agg[NN * DD];
static __device__ float g_y1[NN * DD];
static __device__ float g_y2[NN * 32];
static __device__ float g_cs[NN];
static __device__ float g_cd[NN];
static __device__ float g_alpha1[2 * H1], g_beta1[2 * H1];
static __device__ float g_alpha2[2 * H2], g_beta2[2 * H2];
static __device__ float g_betad[2 * DD];

// ---------------- prep: fold BN into GEMM epilogue vectors ----------------
__global__ void prep_kernel(const float* __restrict__ b1, const float* __restrict__ g1,
                            const float* __restrict__ be1, const float* __restrict__ m1,
                            const float* __restrict__ v1,
                            const float* __restrict__ b2, const float* __restrict__ g2,
                            const float* __restrict__ be2, const float* __restrict__ m2,
                            const float* __restrict__ v2,
                            const float* __restrict__ bd)
{
    int t = threadIdx.x;
    for (int i = t; i < 2 * H1; i += blockDim.x) {
        float a = g1[i] * rsqrtf(v1[i] + 1e-5f);
        g_alpha1[i] = a;
        g_beta1[i]  = (b1[i] - m1[i]) * a + be1[i];
    }
    for (int i = t; i < 2 * H2; i += blockDim.x) {
        float a = g2[i] * rsqrtf(v2[i] + 1e-5f);
        g_alpha2[i] = a;
        g_beta2[i]  = (b2[i] - m2[i]) * a + be2[i];
    }
    for (int i = t; i < 2 * DD; i += blockDim.x)
        g_betad[i] = 0.5f * bd[i];
}

__global__ void zero_kernel(float* __restrict__ p, int n)
{
    int i = blockIdx.x * blockDim.x + threadIdx.x;
    if (i < n) p[i] = 0.0f;
}

__global__ void deg_count_kernel(const int* __restrict__ src, const int* __restrict__ dst)
{
    int i = blockIdx.x * blockDim.x + threadIdx.x;
    if (i < NE) {
        atomicAdd(&g_cs[src[i]], 1.0f);
        atomicAdd(&g_cd[dst[i]], 1.0f);
    }
}

__global__ void deg_finish_kernel()
{
    int i = blockIdx.x * blockDim.x + threadIdx.x;
    if (i < NN) {
        g_cs[i] = rsqrtf(fmaxf(g_cs[i], 1.0f));
        g_cd[i] = rsqrtf(fmaxf(g_cd[i], 1.0f));
    }
}

// ================= TF32 tensor-core GEMM, 128x64 block tile =================
__device__ __forceinline__ unsigned f2tf(float x)
{
    unsigned r;
    asm("cvt.rna.tf32.f32 %0, %1;" : "=r"(r) : "f"(x));
    return r;
}

__device__ __forceinline__ void mma_tf32(float* c, const unsigned* a, const unsigned* b)
{
    asm volatile(
        "mma.sync.aligned.m16n8k8.row.col.f32.tf32.tf32.f32 "
        "{%0,%1,%2,%3}, {%4,%5,%6,%7}, {%8,%9}, {%0,%1,%2,%3};\n"
        : "+f"(c[0]), "+f"(c[1]), "+f"(c[2]), "+f"(c[3])
        : "r"(a[0]), "r"(a[1]), "r"(a[2]), "r"(a[3]), "r"(b[0]), "r"(b[1]));
}

#define TBM 128
#define TBN 64
#define TBK 16
#define AP  20   // As row stride (floats): (20*m + k) mod 32 hits all banks
#define BP  72   // Bs row stride (floats): (72*k + n) mod 32 hits all banks

__global__ __launch_bounds__(256)
void gemm_tc_kernel(const float* __restrict__ A, const float* __restrict__ B,
                    float* __restrict__ C, int M, int K, int Nc,
                    const float* __restrict__ colScale, const float* __restrict__ colBias,
                    const float* __restrict__ rowScale, float scalarAlpha,
                    int accumulate, int relu)
{
    __shared__ float As[2][TBM][AP];
    __shared__ float Bs[2][TBK][BP];

    const int t    = threadIdx.x;
    const int warp = t >> 5;
    const int lane = t & 31;
    const int bm   = blockIdx.y * TBM;
    const int bn   = blockIdx.x * TBN;

    const int wm = (warp >> 1) * 32;   // 0,32,64,96
    const int wn = (warp & 1) * 32;    // 0,32

    // gmem load slots
    const int ar0 = t >> 2;            // 0..63 (A rows; +64 for second)
    const int ak  = (t & 3) * 4;       // k offset 0,4,8,12
    const int bkr = t >> 4;            // 0..15 (B k row)
    const int bn4 = (t & 15) * 4;      // 0..60

    float4 aReg[2];
    float4 bReg;

    const int nTiles = (K + TBK - 1) / TBK;

    // ---- gmem -> regs for tile at k0 ----
    auto load_tile = [&](int k0) {
#pragma unroll
        for (int i = 0; i < 2; i++) {
            int row = bm + ar0 + i * 64;
            float4 v = make_float4(0.f, 0.f, 0.f, 0.f);
            if (row < M) {
                int kk = k0 + ak;
                if (kk + 3 < K) {
                    v = *(const float4*)(A + (size_t)row * K + kk);
                } else {
                    float tmp[4] = {0.f, 0.f, 0.f, 0.f};
#pragma unroll
                    for (int j = 0; j < 4; j++)
                        if (kk + j < K) tmp[j] = A[(size_t)row * K + kk + j];
                    v = make_float4(tmp[0], tmp[1], tmp[2], tmp[3]);
                }
            }
            aReg[i] = v;
        }
        {
            float4 v = make_float4(0.f, 0.f, 0.f, 0.f);
            int kk = k0 + bkr;
            int cc = bn + bn4;
            if (kk < K) {
                if (cc + 3 < Nc) {
                    v = *(const float4*)(B + (size_t)kk * Nc + cc);
                } else {
                    float tmp[4] = {0.f, 0.f, 0.f, 0.f};
#pragma unroll
                    for (int j = 0; j < 4; j++)
                        if (cc + j < Nc) tmp[j] = B[(size_t)kk * Nc + cc + j];
                    v = make_float4(tmp[0], tmp[1], tmp[2], tmp[3]);
                }
            }
            bReg = v;
        }
    };

    auto store_tile = [&](int buf) {
#pragma unroll
        for (int i = 0; i < 2; i++)
            *(float4*)&As[buf][ar0 + i * 64][ak] = aReg[i];
        *(float4*)&Bs[buf][bkr][bn4] = bReg;
    };

    float acc[2][4][4];
#pragma unroll
    for (int mi = 0; mi < 2; mi++)
#pragma unroll
        for (int ni = 0; ni < 4; ni++)
#pragma unroll
            for (int j = 0; j < 4; j++) acc[mi][ni][j] = 0.f;

    load_tile(0);
    store_tile(0);
    __syncthreads();

    for (int tt = 0; tt < nTiles; tt++) {
        const int buf = tt & 1;
        if (tt + 1 < nTiles) load_tile((tt + 1) * TBK);

#pragma unroll
        for (int ks = 0; ks < 2; ks++) {
            const int k0 = ks * 8;
            unsigned af[2][4], bf[4][2];
#pragma unroll
            for (int mi = 0; mi < 2; mi++) {
                int r = wm + mi * 16 + (lane >> 2);
                int c = k0 + (lane & 3);
                af[mi][0] = f2tf(As[buf][r][c]);
                af[mi][1] = f2tf(As[buf][r + 8][c]);
                af[mi][2] = f2tf(As[buf][r][c + 4]);
                af[mi][3] = f2tf(As[buf][r + 8][c + 4]);
            }
#pragma unroll
            for (int ni = 0; ni < 4; ni++) {
                int n  = wn + ni * 8 + (lane >> 2);
                int kk = k0 + (lane & 3);
                bf[ni][0] = f2tf(Bs[buf][kk][n]);
                bf[ni][1] = f2tf(Bs[buf][kk + 4][n]);
            }
#pragma unroll
            for (int mi = 0; mi < 2; mi++)
#pragma unroll
                for (int ni = 0; ni < 4; ni++)
                    mma_tf32(acc[mi][ni], af[mi], bf[ni]);
        }

        if (tt + 1 < nTiles) store_tile(buf ^ 1);
        __syncthreads();
    }

    // ---- fused epilogue ----
#pragma unroll
    for (int mi = 0; mi < 2; mi++) {
        int rbase = bm + wm + mi * 16 + (lane >> 2);
#pragma unroll
        for (int half = 0; half < 2; half++) {
            int row = rbase + half * 8;
            if (row >= M) continue;
            float rs = rowScale ? rowScale[row] : 1.0f;
#pragma unroll
            for (int ni = 0; ni < 4; ni++) {
                int cbase = bn + wn + ni * 8 + 2 * (lane & 3);
#pragma unroll
                for (int j = 0; j < 2; j++) {
                    int col = cbase + j;
                    if (col >= Nc) continue;
                    float csv = colScale ? colScale[col] : scalarAlpha;
                    float v = acc[mi][ni][half * 2 + j] * rs * csv;
                    if (colBias) v += colBias[col];
                    size_t idx = (size_t)row * Nc + col;
                    if (accumulate) v += C[idx];
                    if (relu) v = fmaxf(v, 0.0f);
                    C[idx] = v;
                }
            }
        }
    }
}

// ---------------- SIMT 64x64 GEMM (small graph layers only) ----------------
__global__ __launch_bounds__(256)
void gemm64_kernel(const float* __restrict__ A, const float* __restrict__ B,
                   float* __restrict__ C, int M, int K, int Nc,
                   const float* __restrict__ colScale, const float* __restrict__ colBias,
                   const float* __restrict__ rowScale, float scalarAlpha,
                   int accumulate, int relu)
{
    __shared__ float As[16][64];
    __shared__ float Bs[16][64];

    const int t  = threadIdx.x;
    const int bm = blockIdx.y * 64;
    const int bn = blockIdx.x * 64;

    const int a_row = t >> 2;
    const int a_col = (t & 3) * 4;
    const int b_row = t >> 4;
    const int b_col = (t & 15) * 4;

    const int tx = t & 15;
    const int ty = t >> 4;

    float acc[4][4];
#pragma unroll
    for (int i = 0; i < 4; i++)
#pragma unroll
        for (int j = 0; j < 4; j++) acc[i][j] = 0.0f;

    for (int k0 = 0; k0 < K; k0 += 16) {
        float4 av = make_float4(0.f, 0.f, 0.f, 0.f);
        int ar = bm + a_row;
        if (ar < M) {
            if (k0 + a_col + 3 < K) {
                av = *(const float4*)(A + (size_t)ar * K + k0 + a_col);
            } else {
                float tmp[4] = {0.f, 0.f, 0.f, 0.f};
#pragma unroll
                for (int i = 0; i < 4; i++) {
                    int kk = k0 + a_col + i;
                    if (kk < K) tmp[i] = A[(size_t)ar * K + kk];
                }
                av = make_float4(tmp[0], tmp[1], tmp[2], tmp[3]);
            }
        }
        As[a_col + 0][a_row] = av.x;
        As[a_col + 1][a_row] = av.y;
        As[a_col + 2][a_row] = av.z;
        As[a_col + 3][a_row] = av.w;

        float4 bv = make_float4(0.f, 0.f, 0.f, 0.f);
        int br = k0 + b_row;
        int bc = bn + b_col;
        if (br < K) {
            if (bc + 3 < Nc) {
                bv = *(const float4*)(B + (size_t)br * Nc + bc);
            } else {
                float tmp[4] = {0.f, 0.f, 0.f, 0.f};
#pragma unroll
                for (int i = 0; i < 4; i++) {
                    int cc = bc + i;
                    if (cc < Nc) tmp[i] = B[(size_t)br * Nc + cc];
                }
                bv = make_float4(tmp[0], tmp[1], tmp[2], tmp[3]);
            }
        }
        *(float4*)&Bs[b_row][b_col] = bv;

        __syncthreads();

#pragma unroll
        for (int k = 0; k < 16; k++) {
            float4 a = *(const float4*)&As[k][ty * 4];
            float4 b = *(const float4*)&Bs[k][tx * 4];
            acc[0][0] += a.x * b.x; acc[0][1] += a.x * b.y; acc[0][2] += a.x * b.z; acc[0][3] += a.x * b.w;
            acc[1][0] += a.y * b.x; acc[1][1] += a.y * b.y; acc[1][2] += a.y * b.z; acc[1][3] += a.y * b.w;
            acc[2][0] += a.z * b.x; acc[2][1] += a.z * b.y; acc[2][2] += a.z * b.z; acc[2][3] += a.z * b.w;
            acc[3][0] += a.w * b.x; acc[3][1] += a.w * b.y; acc[3][2] += a.w * b.z; acc[3][3] += a.w * b.w;
        }
        __syncthreads();
    }

#pragma unroll
    for (int i = 0; i < 4; i++) {
        int row = bm + ty * 4 + i;
        if (row >= M) continue;
        float rs = rowScale ? rowScale[row] : 1.0f;
#pragma unroll
        for (int j = 0; j < 4; j++) {
            int col = bn + tx * 4 + j;
            if (col >= Nc) continue;
            float cs = colScale ? colScale[col] : scalarAlpha;
            float v = acc[i][j] * rs * cs;
            if (colBias) v += colBias[col];
            size_t idx = (size_t)row * Nc + col;
            if (accumulate) v += C[idx];
            if (relu) v = fmaxf(v, 0.0f);
            C[idx] = v;
        }
    }
}

// ---------------- edge scatter: agg[dst] += xw[src] ----------------
__global__ void scatter_kernel(const float* __restrict__ xw, float* __restrict__ agg,
                               const int* __restrict__ src, const int* __restrict__ dst,
                               int dout4)
{
    int idx = blockIdx.x * blockDim.x + threadIdx.x;
    int total = NE * dout4;
    if (idx >= total) return;
    int e = idx / dout4;
    int c = (idx - e * dout4) * 4;
    int dout = dout4 * 4;
    int s = src[e], d = dst[e];
    float4 v = *(const float4*)(xw + (size_t)s * dout + c);
    float* p = agg + (size_t)d * dout + c;
    atomicAdd(p + 0, v.x);
    atomicAdd(p + 1, v.y);
    atomicAdd(p + 2, v.z);
    atomicAdd(p + 3, v.w);
}

__global__ void finalize_kernel(const float* __restrict__ agg, float* __restrict__ out,
                                const float* __restrict__ bias, int dout, int relu)
{
    int idx = blockIdx.x * blockDim.x + threadIdx.x;
    if (idx >= NN * dout) return;
    int n = idx / dout;
    int c = idx - n * dout;
    float v = agg[idx] * g_cd[n] + bias[c];
    if (relu) v = fmaxf(v, 0.0f);
    out[idx] = v;
}

// ---------------- launch ----------------
static inline dim3 tc_grid(int M, int Nc)
{
    return dim3((Nc + TBN - 1) / TBN, (M + TBM - 1) / TBM);
}
static inline dim3 gemm_grid(int M, int Nc)
{
    return dim3((Nc + 63) / 64, (M + 63) / 64);
}

extern "C" void kernel_launch(void* const* d_in, const int* in_sizes, int n_in,
                              void* d_out, int out_size)
{
    const float* h   = (const float*)d_in[0];
    const int*   src = (const int*)  d_in[1];
    const int*   dst = (const int*)  d_in[2];
    const float* W1  = (const float*)d_in[3];
    const float* b1  = (const float*)d_in[4];
    const float* g1  = (const float*)d_in[5];
    const float* be1 = (const float*)d_in[6];
    const float* m1  = (const float*)d_in[7];
    const float* v1  = (const float*)d_in[8];
    const float* W2  = (const float*)d_in[9];
    const float* b2  = (const float*)d_in[10];
    const float* g2  = (const float*)d_in[11];
    const float* be2 = (const float*)d_in[12];
    const float* m2  = (const float*)d_in[13];
    const float* v2  = (const float*)d_in[14];
    const float* Wd  = (const float*)d_in[15];
    const float* bd  = (const float*)d_in[16];
    const float* Wg0 = (const float*)d_in[17];
    const float* bg0 = (const float*)d_in[18];
    const float* Wg1 = (const float*)d_in[19];
    const float* bg1 = (const float*)d_in[20];
    const float* Wg2 = (const float*)d_in[21];
    const float* bg2 = (const float*)d_in[22];
    float* out = (float*)d_out;

    float *z1, *z2, *feat, *xw, *agg, *y1, *y2, *cs, *cd;
    float *alpha1, *beta1, *alpha2, *beta2, *betad;
    cudaGetSymbolAddress((void**)&z1, g_z1);
    cudaGetSymbolAddress((void**)&z2, g_z2);
    cudaGetSymbolAddress((void**)&feat, g_feat);
    cudaGetSymbolAddress((void**)&xw, g_xw);
    cudaGetSymbolAddress((void**)&agg, g_agg);
    cudaGetSymbolAddress((void**)&y1, g_y1);
    cudaGetSymbolAddress((void**)&y2, g_y2);
    cudaGetSymbolAddress((void**)&cs, g_cs);
    cudaGetSymbolAddress((void**)&cd, g_cd);
    cudaGetSymbolAddress((void**)&alpha1, g_alpha1);
    cudaGetSymbolAddress((void**)&beta1, g_beta1);
    cudaGetSymbolAddress((void**)&alpha2, g_alpha2);
    cudaGetSymbolAddress((void**)&beta2, g_beta2);
    cudaGetSymbolAddress((void**)&betad, g_betad);

    prep_kernel<<<1, 512>>>(b1, g1, be1, m1, v1, b2, g2, be2, m2, v2, bd);

    zero_kernel<<<(NN + 255) / 256, 256>>>(cs, NN);
    zero_kernel<<<(NN + 255) / 256, 256>>>(cd, NN);
    deg_count_kernel<<<(NE + 255) / 256, 256>>>(src, dst);
    deg_finish_kernel<<<(NN + 255) / 256, 256>>>();

    // encoder layer 1 (tensor cores): z1[m] = BN1(h[m] @ W1[m] + b1[m])
    for (int m = 0; m < 2; m++) {
        gemm_tc_kernel<<<tc_grid(NN, H1), 256>>>(
            h + (size_t)m * NN * DIN, W1 + (size_t)m * DIN * H1,
            z1 + (size_t)m * NN * H1, NN, DIN, H1,
            alpha1 + m * H1, beta1 + m * H1, nullptr, 1.0f, 0, 0);
    }

    // encoder layer 2 (tensor cores)
    for (int m = 0; m < 2; m++) {
        gemm_tc_kernel<<<tc_grid(NN, H2), 256>>>(
            z1 + (size_t)m * NN * H1, W2 + (size_t)m * H1 * H2,
            z2 + (size_t)m * NN * H2, NN, H1, H2,
            alpha2 + m * H2, beta2 + m * H2, nullptr, 1.0f, 0, 0);
    }

    // decoder + modality mean (tensor cores)
    gemm_tc_kernel<<<tc_grid(NN, DD), 256>>>(
        z2, Wd, feat, NN, H2, DD,
        nullptr, betad, nullptr, 0.5f, 0, 0);
    gemm_tc_kernel<<<tc_grid(NN, DD), 256>>>(
        z2 + (size_t)NN * H2, Wd + (size_t)H2 * DD, feat, NN, H2, DD,
        nullptr, betad + DD, nullptr, 0.5f, 1, 0);

    // ---- GraphConv 1: 64 -> 64, relu ----
    zero_kernel<<<(NN * DD + 255) / 256, 256>>>(agg, NN * DD);
    gemm64_kernel<<<gemm_grid(NN, DD), 256>>>(
        feat, Wg0, xw, NN, DD, DD, nullptr, nullptr, cs, 1.0f, 0, 0);
    scatter_kernel<<<(NE * 16 + 255) / 256, 256>>>(xw, agg, src, dst, 16);
    finalize_kernel<<<(NN * DD + 255) / 256, 256>>>(agg, y1, bg0, DD, 1);

    // ---- GraphConv 2: 64 -> 32, relu ----
    zero_kernel<<<(NN * 32 + 255) / 256, 256>>>(agg, NN * 32);
    gemm64_kernel<<<gemm_grid(NN, 32), 256>>>(
        y1, Wg1, xw, NN, DD, 32, nullptr, nullptr, cs, 1.0f, 0, 0);
    scatter_kernel<<<(NE * 8 + 255) / 256, 256>>>(xw, agg, src, dst, 8);
    finalize_kernel<<<(NN * 32 + 255) / 256, 256>>>(agg, y2, bg1, 32, 1);

    // ---- GraphConv 3: 32 -> 4, no relu, write output ----
    zero_kernel<<<(NN * 4 + 255) / 256, 256>>>(agg, NN * 4);
    gemm64_kernel<<<gemm_grid(NN, 4), 256>>>(
        y2, Wg2, xw, NN, 32, 4, nullptr, nullptr, cs, 1.0f, 0, 0);
    scatter_kernel<<<(NE * 1 + 255) / 256, 256>>>(xw, agg, src, dst, 1);
    finalize_kernel<<<(NN * 4 + 255) / 256, 256>>>(agg, out, bg2, 4, 0);
}

// round 6
// speedup vs baseline: 2.7746x; 1.1526x over previous
#include <cuda_runtime.h>
#include <cstdint>

#define NN   50000
#define NE   1600000
#define DIN  2000
#define H1   500
#define H2   128
#define DD   64

// ---------------- scratch (static device globals; no allocation) ----------------
static __device__ float g_hr[2 * NN * DIN];    // 800 MB  tf32-rounded h
static __device__ float g_w1r[2 * DIN * H1];
static __device__ float g_w2r[2 * H1 * H2];
static __device__ float g_wdr[2 * H2 * DD];
static __device__ float g_z1[2 * NN * H1];     // 200 MB
static __device__ float g_z2[2 * NN * H2];     // 51 MB
static __device__ float g_feat[NN * DD];
static __device__ float g_xw[NN * DD];
static __device__ float g_agg[NN * DD];
static __device__ float g_y1[NN * DD];
static __device__ float g_y2[NN * 32];
static __device__ float g_cs[NN];
static __device__ float g_cd[NN];
static __device__ float g_alpha1[2 * H1], g_beta1[2 * H1];
static __device__ float g_alpha2[2 * H2], g_beta2[2 * H2];
static __device__ float g_betad[2 * DD];

// ---------------- tf32 helpers ----------------
__device__ __forceinline__ unsigned f2tf(float x)
{
    unsigned r;
    asm("cvt.rna.tf32.f32 %0, %1;" : "=r"(r) : "f"(x));
    return r;
}

__device__ __forceinline__ void mma_tf32(float* c, const unsigned* a, const unsigned* b)
{
    asm volatile(
        "mma.sync.aligned.m16n8k8.row.col.f32.tf32.tf32.f32 "
        "{%0,%1,%2,%3}, {%4,%5,%6,%7}, {%8,%9}, {%0,%1,%2,%3};\n"
        : "+f"(c[0]), "+f"(c[1]), "+f"(c[2]), "+f"(c[3])
        : "r"(a[0]), "r"(a[1]), "r"(a[2]), "r"(a[3]), "r"(b[0]), "r"(b[1]));
}

__device__ __forceinline__ void cp_async16(uint32_t dst, const void* src, int sz)
{
    asm volatile("cp.async.cg.shared.global [%0], [%1], 16, %2;"
                 :: "r"(dst), "l"(src), "r"(sz));
}

// ---------------- prep: fold BN into GEMM epilogue vectors ----------------
__global__ void prep_kernel(const float* __restrict__ b1, const float* __restrict__ g1,
                            const float* __restrict__ be1, const float* __restrict__ m1,
                            const float* __restrict__ v1,
                            const float* __restrict__ b2, const float* __restrict__ g2,
                            const float* __restrict__ be2, const float* __restrict__ m2,
                            const float* __restrict__ v2,
                            const float* __restrict__ bd)
{
    int t = threadIdx.x;
    for (int i = t; i < 2 * H1; i += blockDim.x) {
        float a = g1[i] * rsqrtf(v1[i] + 1e-5f);
        g_alpha1[i] = a;
        g_beta1[i]  = (b1[i] - m1[i]) * a + be1[i];
    }
    for (int i = t; i < 2 * H2; i += blockDim.x) {
        float a = g2[i] * rsqrtf(v2[i] + 1e-5f);
        g_alpha2[i] = a;
        g_beta2[i]  = (b2[i] - m2[i]) * a + be2[i];
    }
    for (int i = t; i < 2 * DD; i += blockDim.x)
        g_betad[i] = 0.5f * bd[i];
}

// round-to-tf32 copy (element counts are multiples of 4)
__global__ void round_tf32_kernel(const float* __restrict__ in, float* __restrict__ out, int n4)
{
    int i = blockIdx.x * blockDim.x + threadIdx.x;
    if (i < n4) {
        float4 v = ((const float4*)in)[i];
        v.x = __uint_as_float(f2tf(v.x));
        v.y = __uint_as_float(f2tf(v.y));
        v.z = __uint_as_float(f2tf(v.z));
        v.w = __uint_as_float(f2tf(v.w));
        ((float4*)out)[i] = v;
    }
}

__global__ void zero_kernel(float* __restrict__ p, int n)
{
    int i = blockIdx.x * blockDim.x + threadIdx.x;
    if (i < n) p[i] = 0.0f;
}

__global__ void deg_count_kernel(const int* __restrict__ src, const int* __restrict__ dst)
{
    int i = blockIdx.x * blockDim.x + threadIdx.x;
    if (i < NE) {
        atomicAdd(&g_cs[src[i]], 1.0f);
        atomicAdd(&g_cd[dst[i]], 1.0f);
    }
}

__global__ void deg_finish_kernel()
{
    int i = blockIdx.x * blockDim.x + threadIdx.x;
    if (i < NN) {
        g_cs[i] = rsqrtf(fmaxf(g_cs[i], 1.0f));
        g_cd[i] = rsqrtf(fmaxf(g_cd[i], 1.0f));
    }
}

// ================= TF32 tensor-core GEMM, 256x64 block tile, cp.async =================
// All operands must already be tf32-rounded (low 13 mantissa bits zero).
#define TBM 256
#define TBN 64
#define TBK 32
#define APW 36   // As row pitch (words): frag bank = (4r + c) mod 32 -> conflict-free
#define BPW 72   // Bs row pitch (words): frag bank = (8k + n) mod 32 -> conflict-free
#define SMEM_BYTES ((2 * TBM * APW + 2 * TBK * BPW) * 4)

__global__ __launch_bounds__(256, 2)
void gemm_tc_kernel(const float* __restrict__ A, const float* __restrict__ B,
                    float* __restrict__ C, int M, int K, int Nc,
                    const float* __restrict__ colScale, const float* __restrict__ colBias,
                    const float* __restrict__ rowScale, float scalarAlpha,
                    int accumulate, int relu, int roundOut)
{
    extern __shared__ float smem[];
    float* AsBase = smem;                        // [2][TBM*APW]
    float* BsBase = smem + 2 * TBM * APW;        // [2][TBK*BPW]

    const int t    = threadIdx.x;
    const int warp = t >> 5;
    const int lane = t & 31;
    const int bm   = blockIdx.y * TBM;
    const int bn   = blockIdx.x * TBN;
    const int wm   = (warp >> 1) * 64;   // 4 warps along M (64 rows each)
    const int wn   = (warp & 1) * 32;    // 2 warps along N (32 cols each)

    const int ar = t >> 3;               // A: 32 rows/pass, 8 passes
    const int ac = (t & 7) * 4;          // A: 8 16B-chunks per 32-k row
    const int br = t >> 4;               // B: 16 k-rows/pass, 2 passes
    const int bc = (t & 15) * 4;         // B: 16 16B-chunks per 64-n row

    const int nT = (K + TBK - 1) / TBK;

    auto issue = [&](int tt, int buf) {
        const int k0 = tt * TBK;
        float* As = AsBase + buf * (TBM * APW);
        float* Bs = BsBase + buf * (TBK * BPW);
        const int aok = (k0 + ac) < K;       // K % 4 == 0 for all layers
#pragma unroll
        for (int i = 0; i < 8; i++) {
            int m  = ar + i * 32;
            int sz = (aok && (bm + m) < M) ? 16 : 0;
            cp_async16((uint32_t)__cvta_generic_to_shared(As + m * APW + ac),
                       A + (size_t)(bm + m) * K + k0 + ac, sz);
        }
        const int bok = (bn + bc) < Nc;      // Nc % 4 == 0 for all layers
#pragma unroll
        for (int i = 0; i < 2; i++) {
            int k  = br + i * 16;
            int sz = (bok && (k0 + k) < K) ? 16 : 0;
            cp_async16((uint32_t)__cvta_generic_to_shared(Bs + k * BPW + bc),
                       B + (size_t)(k0 + k) * Nc + bn + bc, sz);
        }
        asm volatile("cp.async.commit_group;");
    };

    float acc[4][4][4];
#pragma unroll
    for (int mi = 0; mi < 4; mi++)
#pragma unroll
        for (int ni = 0; ni < 4; ni++)
#pragma unroll
            for (int j = 0; j < 4; j++) acc[mi][ni][j] = 0.f;

    issue(0, 0);

    for (int tt = 0; tt < nT; tt++) {
        asm volatile("cp.async.wait_group 0;");
        __syncthreads();
        if (tt + 1 < nT) issue(tt + 1, (tt + 1) & 1);

        const float* As = AsBase + (tt & 1) * (TBM * APW);
        const float* Bs = BsBase + (tt & 1) * (TBK * BPW);

#pragma unroll
        for (int ks = 0; ks < 4; ks++) {
            unsigned bf[4][2];
#pragma unroll
            for (int ni = 0; ni < 4; ni++) {
                int n = wn + ni * 8 + (lane >> 2);
                int k = ks * 8 + (lane & 3);
                bf[ni][0] = __float_as_uint(Bs[k * BPW + n]);
                bf[ni][1] = __float_as_uint(Bs[(k + 4) * BPW + n]);
            }
#pragma unroll
            for (int mi = 0; mi < 4; mi++) {
                int r = wm + mi * 16 + (lane >> 2);
                int c = ks * 8 + (lane & 3);
                unsigned af[4];
                af[0] = __float_as_uint(As[r * APW + c]);
                af[1] = __float_as_uint(As[(r + 8) * APW + c]);
                af[2] = __float_as_uint(As[r * APW + c + 4]);
                af[3] = __float_as_uint(As[(r + 8) * APW + c + 4]);
#pragma unroll
                for (int ni = 0; ni < 4; ni++)
                    mma_tf32(acc[mi][ni], af, bf[ni]);
            }
        }
        __syncthreads();
    }

    // ---- fused epilogue (same fragment mapping as verified R3 kernel) ----
#pragma unroll
    for (int mi = 0; mi < 4; mi++) {
        int rbase = bm + wm + mi * 16 + (lane >> 2);
#pragma unroll
        for (int half = 0; half < 2; half++) {
            int row = rbase + half * 8;
            if (row >= M) continue;
            float rs = rowScale ? rowScale[row] : 1.0f;
#pragma unroll
            for (int ni = 0; ni < 4; ni++) {
                int cbase = bn + wn + ni * 8 + 2 * (lane & 3);
#pragma unroll
                for (int j = 0; j < 2; j++) {
                    int col = cbase + j;
                    if (col >= Nc) continue;
                    float csv = colScale ? colScale[col] : scalarAlpha;
                    float v = acc[mi][ni][half * 2 + j] * rs * csv;
                    if (colBias) v += colBias[col];
                    size_t idx = (size_t)row * Nc + col;
                    if (accumulate) v += C[idx];
                    if (relu) v = fmaxf(v, 0.0f);
                    if (roundOut) v = __uint_as_float(f2tf(v));
                    C[idx] = v;
                }
            }
        }
    }
}

// ---------------- SIMT 64x64 GEMM (small graph layers only) ----------------
__global__ __launch_bounds__(256)
void gemm64_kernel(const float* __restrict__ A, const float* __restrict__ B,
                   float* __restrict__ C, int M, int K, int Nc,
                   const float* __restrict__ colScale, const float* __restrict__ colBias,
                   const float* __restrict__ rowScale, float scalarAlpha,
                   int accumulate, int relu)
{
    __shared__ float As[16][64];
    __shared__ float Bs[16][64];

    const int t  = threadIdx.x;
    const int bm = blockIdx.y * 64;
    const int bn = blockIdx.x * 64;

    const int a_row = t >> 2;
    const int a_col = (t & 3) * 4;
    const int b_row = t >> 4;
    const int b_col = (t & 15) * 4;

    const int tx = t & 15;
    const int ty = t >> 4;

    float acc[4][4];
#pragma unroll
    for (int i = 0; i < 4; i++)
#pragma unroll
        for (int j = 0; j < 4; j++) acc[i][j] = 0.0f;

    for (int k0 = 0; k0 < K; k0 += 16) {
        float4 av = make_float4(0.f, 0.f, 0.f, 0.f);
        int ar = bm + a_row;
        if (ar < M) {
            if (k0 + a_col + 3 < K) {
                av = *(const float4*)(A + (size_t)ar * K + k0 + a_col);
            } else {
                float tmp[4] = {0.f, 0.f, 0.f, 0.f};
#pragma unroll
                for (int i = 0; i < 4; i++) {
                    int kk = k0 + a_col + i;
                    if (kk < K) tmp[i] = A[(size_t)ar * K + kk];
                }
                av = make_float4(tmp[0], tmp[1], tmp[2], tmp[3]);
            }
        }
        As[a_col + 0][a_row] = av.x;
        As[a_col + 1][a_row] = av.y;
        As[a_col + 2][a_row] = av.z;
        As[a_col + 3][a_row] = av.w;

        float4 bv = make_float4(0.f, 0.f, 0.f, 0.f);
        int brr = k0 + b_row;
        int bcc = bn + b_col;
        if (brr < K) {
            if (bcc + 3 < Nc) {
                bv = *(const float4*)(B + (size_t)brr * Nc + bcc);
            } else {
                float tmp[4] = {0.f, 0.f, 0.f, 0.f};
#pragma unroll
                for (int i = 0; i < 4; i++) {
                    int cc = bcc + i;
                    if (cc < Nc) tmp[i] = B[(size_t)brr * Nc + cc];
                }
                bv = make_float4(tmp[0], tmp[1], tmp[2], tmp[3]);
            }
        }
        *(float4*)&Bs[b_row][b_col] = bv;

        __syncthreads();

#pragma unroll
        for (int k = 0; k < 16; k++) {
            float4 a = *(const float4*)&As[k][ty * 4];
            float4 b = *(const float4*)&Bs[k][tx * 4];
            acc[0][0] += a.x * b.x; acc[0][1] += a.x * b.y; acc[0][2] += a.x * b.z; acc[0][3] += a.x * b.w;
            acc[1][0] += a.y * b.x; acc[1][1] += a.y * b.y; acc[1][2] += a.y * b.z; acc[1][3] += a.y * b.w;
            acc[2][0] += a.z * b.x; acc[2][1] += a.z * b.y; acc[2][2] += a.z * b.z; acc[2][3] += a.z * b.w;
            acc[3][0] += a.w * b.x; acc[3][1] += a.w * b.y; acc[3][2] += a.w * b.z; acc[3][3] += a.w * b.w;
        }
        __syncthreads();
    }

#pragma unroll
    for (int i = 0; i < 4; i++) {
        int row = bm + ty * 4 + i;
        if (row >= M) continue;
        float rs = rowScale ? rowScale[row] : 1.0f;
#pragma unroll
        for (int j = 0; j < 4; j++) {
            int col = bn + tx * 4 + j;
            if (col >= Nc) continue;
            float cs = colScale ? colScale[col] : scalarAlpha;
            float v = acc[i][j] * rs * cs;
            if (colBias) v += colBias[col];
            size_t idx = (size_t)row * Nc + col;
            if (accumulate) v += C[idx];
            if (relu) v = fmaxf(v, 0.0f);
            C[idx] = v;
        }
    }
}

// ---------------- edge scatter: agg[dst] += xw[src] ----------------
__global__ void scatter_kernel(const float* __restrict__ xw, float* __restrict__ agg,
                               const int* __restrict__ src, const int* __restrict__ dst,
                               int dout4)
{
    int idx = blockIdx.x * blockDim.x + threadIdx.x;
    int total = NE * dout4;
    if (idx >= total) return;
    int e = idx / dout4;
    int c = (idx - e * dout4) * 4;
    int dout = dout4 * 4;
    int s = src[e], d = dst[e];
    float4 v = *(const float4*)(xw + (size_t)s * dout + c);
    float* p = agg + (size_t)d * dout + c;
    atomicAdd(p + 0, v.x);
    atomicAdd(p + 1, v.y);
    atomicAdd(p + 2, v.z);
    atomicAdd(p + 3, v.w);
}

__global__ void finalize_kernel(const float* __restrict__ agg, float* __restrict__ out,
                                const float* __restrict__ bias, int dout, int relu)
{
    int idx = blockIdx.x * blockDim.x + threadIdx.x;
    if (idx >= NN * dout) return;
    int n = idx / dout;
    int c = idx - n * dout;
    float v = agg[idx] * g_cd[n] + bias[c];
    if (relu) v = fmaxf(v, 0.0f);
    out[idx] = v;
}

// ---------------- launch ----------------
static inline dim3 tc_grid(int M, int Nc)
{
    return dim3((Nc + TBN - 1) / TBN, (M + TBM - 1) / TBM);
}
static inline dim3 gemm_grid(int M, int Nc)
{
    return dim3((Nc + 63) / 64, (M + 63) / 64);
}

extern "C" void kernel_launch(void* const* d_in, const int* in_sizes, int n_in,
                              void* d_out, int out_size)
{
    const float* h   = (const float*)d_in[0];
    const int*   src = (const int*)  d_in[1];
    const int*   dst = (const int*)  d_in[2];
    const float* W1  = (const float*)d_in[3];
    const float* b1  = (const float*)d_in[4];
    const float* g1  = (const float*)d_in[5];
    const float* be1 = (const float*)d_in[6];
    const float* m1  = (const float*)d_in[7];
    const float* v1  = (const float*)d_in[8];
    const float* W2  = (const float*)d_in[9];
    const float* b2  = (const float*)d_in[10];
    const float* g2  = (const float*)d_in[11];
    const float* be2 = (const float*)d_in[12];
    const float* m2  = (const float*)d_in[13];
    const float* v2  = (const float*)d_in[14];
    const float* Wd  = (const float*)d_in[15];
    const float* bd  = (const float*)d_in[16];
    const float* Wg0 = (const float*)d_in[17];
    const float* bg0 = (const float*)d_in[18];
    const float* Wg1 = (const float*)d_in[19];
    const float* bg1 = (const float*)d_in[20];
    const float* Wg2 = (const float*)d_in[21];
    const float* bg2 = (const float*)d_in[22];
    float* out = (float*)d_out;

    float *hr, *w1r, *w2r, *wdr;
    float *z1, *z2, *feat, *xw, *agg, *y1, *y2, *cs, *cd;
    float *alpha1, *beta1, *alpha2, *beta2, *betad;
    cudaGetSymbolAddress((void**)&hr, g_hr);
    cudaGetSymbolAddress((void**)&w1r, g_w1r);
    cudaGetSymbolAddress((void**)&w2r, g_w2r);
    cudaGetSymbolAddress((void**)&wdr, g_wdr);
    cudaGetSymbolAddress((void**)&z1, g_z1);
    cudaGetSymbolAddress((void**)&z2, g_z2);
    cudaGetSymbolAddress((void**)&feat, g_feat);
    cudaGetSymbolAddress((void**)&xw, g_xw);
    cudaGetSymbolAddress((void**)&agg, g_agg);
    cudaGetSymbolAddress((void**)&y1, g_y1);
    cudaGetSymbolAddress((void**)&y2, g_y2);
    cudaGetSymbolAddress((void**)&cs, g_cs);
    cudaGetSymbolAddress((void**)&cd, g_cd);
    cudaGetSymbolAddress((void**)&alpha1, g_alpha1);
    cudaGetSymbolAddress((void**)&beta1, g_beta1);
    cudaGetSymbolAddress((void**)&alpha2, g_alpha2);
    cudaGetSymbolAddress((void**)&beta2, g_beta2);
    cudaGetSymbolAddress((void**)&betad, g_betad);

    cudaFuncSetAttribute(gemm_tc_kernel, cudaFuncAttributeMaxDynamicSharedMemorySize, SMEM_BYTES);

    prep_kernel<<<1, 512>>>(b1, g1, be1, m1, v1, b2, g2, be2, m2, v2, bd);

    // tf32 pre-rounding of GEMM operands
    {
        int n4 = 2 * NN * DIN / 4;
        round_tf32_kernel<<<(n4 + 255) / 256, 256>>>(h, hr, n4);
        n4 = 2 * DIN * H1 / 4;
        round_tf32_kernel<<<(n4 + 255) / 256, 256>>>(W1, w1r, n4);
        n4 = 2 * H1 * H2 / 4;
        round_tf32_kernel<<<(n4 + 255) / 256, 256>>>(W2, w2r, n4);
        n4 = 2 * H2 * DD / 4;
        round_tf32_kernel<<<(n4 + 255) / 256, 256>>>(Wd, wdr, n4);
    }

    zero_kernel<<<(NN + 255) / 256, 256>>>(cs, NN);
    zero_kernel<<<(NN + 255) / 256, 256>>>(cd, NN);
    deg_count_kernel<<<(NE + 255) / 256, 256>>>(src, dst);
    deg_finish_kernel<<<(NN + 255) / 256, 256>>>();

    // encoder layer 1: z1[m] = BN1(h[m] @ W1[m] + b1[m]); z1 tf32-rounded for enc2
    for (int m = 0; m < 2; m++) {
        gemm_tc_kernel<<<tc_grid(NN, H1), 256, SMEM_BYTES>>>(
            hr + (size_t)m * NN * DIN, w1r + (size_t)m * DIN * H1,
            z1 + (size_t)m * NN * H1, NN, DIN, H1,
            alpha1 + m * H1, beta1 + m * H1, nullptr, 1.0f, 0, 0, 1);
    }

    // encoder layer 2: z2 tf32-rounded for dec
    for (int m = 0; m < 2; m++) {
        gemm_tc_kernel<<<tc_grid(NN, H2), 256, SMEM_BYTES>>>(
            z1 + (size_t)m * NN * H1, w2r + (size_t)m * H1 * H2,
            z2 + (size_t)m * NN * H2, NN, H1, H2,
            alpha2 + m * H2, beta2 + m * H2, nullptr, 1.0f, 0, 0, 1);
    }

    // decoder + modality mean (feat stays full fp32 for the SIMT graph GEMMs)
    gemm_tc_kernel<<<tc_grid(NN, DD), 256, SMEM_BYTES>>>(
        z2, wdr, feat, NN, H2, DD,
        nullptr, betad, nullptr, 0.5f, 0, 0, 0);
    gemm_tc_kernel<<<tc_grid(NN, DD), 256, SMEM_BYTES>>>(
        z2 + (size_t)NN * H2, wdr + (size_t)H2 * DD, feat, NN, H2, DD,
        nullptr, betad + DD, nullptr, 0.5f, 1, 0, 0);

    // ---- GraphConv 1: 64 -> 64, relu ----
    zero_kernel<<<(NN * DD + 255) / 256, 256>>>(agg, NN * DD);
    gemm64_kernel<<<gemm_grid(NN, DD), 256>>>(
        feat, Wg0, xw, NN, DD, DD, nullptr, nullptr, cs, 1.0f, 0, 0);
    scatter_kernel<<<(NE * 16 + 255) / 256, 256>>>(xw, agg, src, dst, 16);
    finalize_kernel<<<(NN * DD + 255) / 256, 256>>>(agg, y1, bg0, DD, 1);

    // ---- GraphConv 2: 64 -> 32, relu ----
    zero_kernel<<<(NN * 32 + 255) / 256, 256>>>(agg, NN * 32);
    gemm64_kernel<<<gemm_grid(NN, 32), 256>>>(
        y1, Wg1, xw, NN, DD, 32, nullptr, nullptr, cs, 1.0f, 0, 0);
    scatter_kernel<<<(NE * 8 + 255) / 256, 256>>>(xw, agg, src, dst, 8);
    finalize_kernel<<<(NN * 32 + 255) / 256, 256>>>(agg, y2, bg1, 32, 1);

    // ---- GraphConv 3: 32 -> 4, no relu, write output ----
    zero_kernel<<<(NN * 4 + 255) / 256, 256>>>(agg, NN * 4);
    gemm64_kernel<<<gemm_grid(NN, 4), 256>>>(
        y2, Wg2, xw, NN, 32, 4, nullptr, nullptr, cs, 1.0f, 0, 0);
    scatter_kernel<<<(NE * 1 + 255) / 256, 256>>>(xw, agg, src, dst, 1);
    finalize_kernel<<<(NN * 4 + 255) / 256, 256>>>(agg, out, bg2, 4, 0);
}

// round 7
// speedup vs baseline: 3.4677x; 1.2498x over previous
#include <cuda_runtime.h>
#include <cstdint>

#define NN   50000
#define NE   1600000
#define DIN  2000
#define H1   500
#define H2   128
#define DD   64

// ---------------- scratch (static device globals; no allocation) ----------------
static __device__ float g_w1r[2 * DIN * H1];
static __device__ float g_w2r[2 * H1 * H2];
static __device__ float g_wdr[2 * H2 * DD];
static __device__ float g_z1[2 * NN * H1];     // 200 MB
static __device__ float g_z2[2 * NN * H2];     // 51 MB
static __device__ float g_feat[NN * DD];
static __device__ float g_xw[NN * DD];
static __device__ float g_agg[NN * DD];
static __device__ float g_y1[NN * DD];
static __device__ float g_y2[NN * 32];
static __device__ float g_cs[NN];
static __device__ float g_cd[NN];
static __device__ float g_alpha1[2 * H1], g_beta1[2 * H1];
static __device__ float g_alpha2[2 * H2], g_beta2[2 * H2];
static __device__ float g_betad[2 * DD];

// ---------------- tf32 helpers ----------------
__device__ __forceinline__ unsigned f2tf(float x)
{
    unsigned r;
    asm("cvt.rna.tf32.f32 %0, %1;" : "=r"(r) : "f"(x));
    return r;
}
__device__ __forceinline__ float f2tff(float x) { return __uint_as_float(f2tf(x)); }

__device__ __forceinline__ void mma_tf32(float* c, const unsigned* a, const unsigned* b)
{
    asm volatile(
        "mma.sync.aligned.m16n8k8.row.col.f32.tf32.tf32.f32 "
        "{%0,%1,%2,%3}, {%4,%5,%6,%7}, {%8,%9}, {%0,%1,%2,%3};\n"
        : "+f"(c[0]), "+f"(c[1]), "+f"(c[2]), "+f"(c[3])
        : "r"(a[0]), "r"(a[1]), "r"(a[2]), "r"(a[3]), "r"(b[0]), "r"(b[1]));
}

__device__ __forceinline__ void cp_async16(uint32_t dst, const void* src, int sz)
{
    asm volatile("cp.async.cg.shared.global [%0], [%1], 16, %2;"
                 :: "r"(dst), "l"(src), "r"(sz));
}

// ---------------- prep: fold BN into GEMM epilogue vectors ----------------
__global__ void prep_kernel(const float* __restrict__ b1, const float* __restrict__ g1,
                            const float* __restrict__ be1, const float* __restrict__ m1,
                            const float* __restrict__ v1,
                            const float* __restrict__ b2, const float* __restrict__ g2,
                            const float* __restrict__ be2, const float* __restrict__ m2,
                            const float* __restrict__ v2,
                            const float* __restrict__ bd)
{
    int t = threadIdx.x;
    for (int i = t; i < 2 * H1; i += blockDim.x) {
        float a = g1[i] * rsqrtf(v1[i] + 1e-5f);
        g_alpha1[i] = a;
        g_beta1[i]  = (b1[i] - m1[i]) * a + be1[i];
    }
    for (int i = t; i < 2 * H2; i += blockDim.x) {
        float a = g2[i] * rsqrtf(v2[i] + 1e-5f);
        g_alpha2[i] = a;
        g_beta2[i]  = (b2[i] - m2[i]) * a + be2[i];
    }
    for (int i = t; i < 2 * DD; i += blockDim.x)
        g_betad[i] = 0.5f * bd[i];
}

// round-to-tf32 copy (element counts are multiples of 4) — weights only
__global__ void round_tf32_kernel(const float* __restrict__ in, float* __restrict__ out, int n4)
{
    int i = blockIdx.x * blockDim.x + threadIdx.x;
    if (i < n4) {
        float4 v = ((const float4*)in)[i];
        v.x = f2tff(v.x); v.y = f2tff(v.y); v.z = f2tff(v.z); v.w = f2tff(v.w);
        ((float4*)out)[i] = v;
    }
}

__global__ void zero_kernel(float* __restrict__ p, int n)
{
    int i = blockIdx.x * blockDim.x + threadIdx.x;
    if (i < n) p[i] = 0.0f;
}

__global__ void deg_count_kernel(const int* __restrict__ src, const int* __restrict__ dst)
{
    int i = blockIdx.x * blockDim.x + threadIdx.x;
    if (i < NE) {
        atomicAdd(&g_cs[src[i]], 1.0f);
        atomicAdd(&g_cd[dst[i]], 1.0f);
    }
}

__global__ void deg_finish_kernel()
{
    int i = blockIdx.x * blockDim.x + threadIdx.x;
    if (i < NN) {
        g_cs[i] = rsqrtf(fmaxf(g_cs[i], 1.0f));
        g_cd[i] = rsqrtf(fmaxf(g_cd[i], 1.0f));
    }
}

// ================= TF32 tensor-core GEMM, 128x128 block / 64x64 warp tile ============
// A: fp32 (tf32-rounded on load), B: must be pre-rounded tf32.
#define TBM 128
#define TBN 128
#define TBK 32
#define APW 36    // bank = (4r + c) mod 32 -> conflict-free fragment loads
#define BPW 136   // bank = (8k + n) mod 32 -> conflict-free fragment loads
#define SMEM_BYTES ((2 * TBM * APW + 2 * TBK * BPW) * 4)

__global__ __launch_bounds__(128, 2)
void gemm_tc_kernel(const float* __restrict__ A, const float* __restrict__ B,
                    float* __restrict__ C, int M, int K, int Nc,
                    const float* __restrict__ colScale, const float* __restrict__ colBias,
                    const float* __restrict__ rowScale, float scalarAlpha,
                    int accumulate, int relu, int roundOut)
{
    extern __shared__ float smem[];
    float* AsBase = smem;                        // [2][TBM*APW]
    float* BsBase = smem + 2 * TBM * APW;        // [2][TBK*BPW]

    const int t    = threadIdx.x;
    const int warp = t >> 5;
    const int lane = t & 31;
    const int bm   = blockIdx.y * TBM;
    const int bn   = blockIdx.x * TBN;
    const int wm   = (warp >> 1) * 64;   // 2 warps along M
    const int wn   = (warp & 1) * 64;    // 2 warps along N

    const int aRow = t >> 3;             // 0..15 (A rows, 8 passes of 16)
    const int aCol = (t & 7) * 4;        // 0..28
    const int bRow = t >> 5;             // 0..3  (B k-rows, 8 passes of 4)
    const int bCol = (t & 31) * 4;       // 0..124

    const int nT = (K + TBK - 1) / TBK;

    float4 aReg[8];

    auto ldgA = [&](int k0) {
#pragma unroll
        for (int i = 0; i < 8; i++) {
            int row = bm + aRow + i * 16;
            int kk  = k0 + aCol;
            float4 v = make_float4(0.f, 0.f, 0.f, 0.f);
            if (row < M && kk < K)   // K % 4 == 0 -> full chunk valid
                v = *(const float4*)(A + (size_t)row * K + kk);
            v.x = f2tff(v.x); v.y = f2tff(v.y); v.z = f2tff(v.z); v.w = f2tff(v.w);
            aReg[i] = v;
        }
    };
    auto stsA = [&](int buf) {
        float* As = AsBase + buf * (TBM * APW);
#pragma unroll
        for (int i = 0; i < 8; i++)
            *(float4*)(As + (aRow + i * 16) * APW + aCol) = aReg[i];
    };
    auto cpB = [&](int k0, int buf) {
        float* Bs = BsBase + buf * (TBK * BPW);
        const int cc = bn + bCol;
#pragma unroll
        for (int i = 0; i < 8; i++) {
            int k  = bRow + i * 4;
            int sz = ((k0 + k) < K && cc < Nc) ? 16 : 0;   // Nc % 4 == 0
            cp_async16((uint32_t)__cvta_generic_to_shared(Bs + k * BPW + bCol),
                       B + (size_t)(k0 + k) * Nc + cc, sz);
        }
        asm volatile("cp.async.commit_group;");
    };

    float acc[4][8][4];
#pragma unroll
    for (int mi = 0; mi < 4; mi++)
#pragma unroll
        for (int ni = 0; ni < 8; ni++)
#pragma unroll
            for (int j = 0; j < 4; j++) acc[mi][ni][j] = 0.f;

    ldgA(0);
    cpB(0, 0);

    for (int tt = 0; tt < nT; tt++) {
        const int buf = tt & 1;
        stsA(buf);
        asm volatile("cp.async.wait_group 0;");
        __syncthreads();
        if (tt + 1 < nT) {
            ldgA((tt + 1) * TBK);
            cpB((tt + 1) * TBK, buf ^ 1);
        }

        const float* As = AsBase + buf * (TBM * APW);
        const float* Bs = BsBase + buf * (TBK * BPW);

#pragma unroll
        for (int ks = 0; ks < 4; ks++) {
            const int c = ks * 8 + (lane & 3);
            unsigned bf[8][2];
#pragma unroll
            for (int ni = 0; ni < 8; ni++) {
                int n = wn + ni * 8 + (lane >> 2);
                bf[ni][0] = __float_as_uint(Bs[c * BPW + n]);
                bf[ni][1] = __float_as_uint(Bs[(c + 4) * BPW + n]);
            }
#pragma unroll
            for (int mi = 0; mi < 4; mi++) {
                int r = wm + mi * 16 + (lane >> 2);
                unsigned af[4];
                af[0] = __float_as_uint(As[r * APW + c]);
                af[1] = __float_as_uint(As[(r + 8) * APW + c]);
                af[2] = __float_as_uint(As[r * APW + c + 4]);
                af[3] = __float_as_uint(As[(r + 8) * APW + c + 4]);
#pragma unroll
                for (int ni = 0; ni < 8; ni++)
                    mma_tf32(acc[mi][ni], af, bf[ni]);
            }
        }
        __syncthreads();
    }

    // ---- fused epilogue (fragment mapping identical to verified R3/R6 kernels) ----
#pragma unroll
    for (int mi = 0; mi < 4; mi++) {
        int rbase = bm + wm + mi * 16 + (lane >> 2);
#pragma unroll
        for (int half = 0; half < 2; half++) {
            int row = rbase + half * 8;
            if (row >= M) continue;
            float rs = rowScale ? rowScale[row] : 1.0f;
#pragma unroll
            for (int ni = 0; ni < 8; ni++) {
                int cbase = bn + wn + ni * 8 + 2 * (lane & 3);
#pragma unroll
                for (int j = 0; j < 2; j++) {
                    int col = cbase + j;
                    if (col >= Nc) continue;
                    float csv = colScale ? colScale[col] : scalarAlpha;
                    float v = acc[mi][ni][half * 2 + j] * rs * csv;
                    if (colBias) v += colBias[col];
                    size_t idx = (size_t)row * Nc + col;
                    if (accumulate) v += C[idx];
                    if (relu) v = fmaxf(v, 0.0f);
                    if (roundOut) v = f2tff(v);
                    C[idx] = v;
                }
            }
        }
    }
}

// ---------------- SIMT 64x64 GEMM (small graph layers only) ----------------
__global__ __launch_bounds__(256)
void gemm64_kernel(const float* __restrict__ A, const float* __restrict__ B,
                   float* __restrict__ C, int M, int K, int Nc,
                   const float* __restrict__ colScale, const float* __restrict__ colBias,
                   const float* __restrict__ rowScale, float scalarAlpha,
                   int accumulate, int relu)
{
    __shared__ float As[16][64];
    __shared__ float Bs[16][64];

    const int t  = threadIdx.x;
    const int bm = blockIdx.y * 64;
    const int bn = blockIdx.x * 64;

    const int a_row = t >> 2;
    const int a_col = (t & 3) * 4;
    const int b_row = t >> 4;
    const int b_col = (t & 15) * 4;

    const int tx = t & 15;
    const int ty = t >> 4;

    float acc[4][4];
#pragma unroll
    for (int i = 0; i < 4; i++)
#pragma unroll
        for (int j = 0; j < 4; j++) acc[i][j] = 0.0f;

    for (int k0 = 0; k0 < K; k0 += 16) {
        float4 av = make_float4(0.f, 0.f, 0.f, 0.f);
        int ar = bm + a_row;
        if (ar < M) {
            if (k0 + a_col + 3 < K) {
                av = *(const float4*)(A + (size_t)ar * K + k0 + a_col);
            } else {
                float tmp[4] = {0.f, 0.f, 0.f, 0.f};
#pragma unroll
                for (int i = 0; i < 4; i++) {
                    int kk = k0 + a_col + i;
                    if (kk < K) tmp[i] = A[(size_t)ar * K + kk];
                }
                av = make_float4(tmp[0], tmp[1], tmp[2], tmp[3]);
            }
        }
        As[a_col + 0][a_row] = av.x;
        As[a_col + 1][a_row] = av.y;
        As[a_col + 2][a_row] = av.z;
        As[a_col + 3][a_row] = av.w;

        float4 bv = make_float4(0.f, 0.f, 0.f, 0.f);
        int brr = k0 + b_row;
        int bcc = bn + b_col;
        if (brr < K) {
            if (bcc + 3 < Nc) {
                bv = *(const float4*)(B + (size_t)brr * Nc + bcc);
            } else {
                float tmp[4] = {0.f, 0.f, 0.f, 0.f};
#pragma unroll
                for (int i = 0; i < 4; i++) {
                    int cc = bcc + i;
                    if (cc < Nc) tmp[i] = B[(size_t)brr * Nc + cc];
                }
                bv = make_float4(tmp[0], tmp[1], tmp[2], tmp[3]);
            }
        }
        *(float4*)&Bs[b_row][b_col] = bv;

        __syncthreads();

#pragma unroll
        for (int k = 0; k < 16; k++) {
            float4 a = *(const float4*)&As[k][ty * 4];
            float4 b = *(const float4*)&Bs[k][tx * 4];
            acc[0][0] += a.x * b.x; acc[0][1] += a.x * b.y; acc[0][2] += a.x * b.z; acc[0][3] += a.x * b.w;
            acc[1][0] += a.y * b.x; acc[1][1] += a.y * b.y; acc[1][2] += a.y * b.z; acc[1][3] += a.y * b.w;
            acc[2][0] += a.z * b.x; acc[2][1] += a.z * b.y; acc[2][2] += a.z * b.z; acc[2][3] += a.z * b.w;
            acc[3][0] += a.w * b.x; acc[3][1] += a.w * b.y; acc[3][2] += a.w * b.z; acc[3][3] += a.w * b.w;
        }
        __syncthreads();
    }

#pragma unroll
    for (int i = 0; i < 4; i++) {
        int row = bm + ty * 4 + i;
        if (row >= M) continue;
        float rs = rowScale ? rowScale[row] : 1.0f;
#pragma unroll
        for (int j = 0; j < 4; j++) {
            int col = bn + tx * 4 + j;
            if (col >= Nc) continue;
            float cs = colScale ? colScale[col] : scalarAlpha;
            float v = acc[i][j] * rs * cs;
            if (colBias) v += colBias[col];
            size_t idx = (size_t)row * Nc + col;
            if (accumulate) v += C[idx];
            if (relu) v = fmaxf(v, 0.0f);
            C[idx] = v;
        }
    }
}

// ---------------- edge scatter: agg[dst] += xw[src] (vector reductions) ----------------
__global__ void scatter_kernel(const float* __restrict__ xw, float* __restrict__ agg,
                               const int* __restrict__ src, const int* __restrict__ dst,
                               int dout4)
{
    int idx = blockIdx.x * blockDim.x + threadIdx.x;
    int total = NE * dout4;
    if (idx >= total) return;
    int e = idx / dout4;
    int c = (idx - e * dout4) * 4;
    int dout = dout4 * 4;
    int s = src[e], d = dst[e];
    float4 v = *(const float4*)(xw + (size_t)s * dout + c);
    float* p = agg + (size_t)d * dout + c;
    asm volatile("red.global.add.v4.f32 [%0], {%1, %2, %3, %4};"
                 :: "l"(p), "f"(v.x), "f"(v.y), "f"(v.z), "f"(v.w) : "memory");
}

__global__ void finalize_kernel(const float* __restrict__ agg, float* __restrict__ out,
                                const float* __restrict__ bias, int dout, int relu)
{
    int idx = blockIdx.x * blockDim.x + threadIdx.x;
    if (idx >= NN * dout) return;
    int n = idx / dout;
    int c = idx - n * dout;
    float v = agg[idx] * g_cd[n] + bias[c];
    if (relu) v = fmaxf(v, 0.0f);
    out[idx] = v;
}

// ---------------- launch ----------------
static inline dim3 tc_grid(int M, int Nc)
{
    return dim3((Nc + TBN - 1) / TBN, (M + TBM - 1) / TBM);
}
static inline dim3 gemm_grid(int M, int Nc)
{
    return dim3((Nc + 63) / 64, (M + 63) / 64);
}

extern "C" void kernel_launch(void* const* d_in, const int* in_sizes, int n_in,
                              void* d_out, int out_size)
{
    const float* h   = (const float*)d_in[0];
    const int*   src = (const int*)  d_in[1];
    const int*   dst = (const int*)  d_in[2];
    const float* W1  = (const float*)d_in[3];
    const float* b1  = (const float*)d_in[4];
    const float* g1  = (const float*)d_in[5];
    const float* be1 = (const float*)d_in[6];
    const float* m1  = (const float*)d_in[7];
    const float* v1  = (const float*)d_in[8];
    const float* W2  = (const float*)d_in[9];
    const float* b2  = (const float*)d_in[10];
    const float* g2  = (const float*)d_in[11];
    const float* be2 = (const float*)d_in[12];
    const float* m2  = (const float*)d_in[13];
    const float* v2  = (const float*)d_in[14];
    const float* Wd  = (const float*)d_in[15];
    const float* bd  = (const float*)d_in[16];
    const float* Wg0 = (const float*)d_in[17];
    const float* bg0 = (const float*)d_in[18];
    const float* Wg1 = (const float*)d_in[19];
    const float* bg1 = (const float*)d_in[20];
    const float* Wg2 = (const float*)d_in[21];
    const float* bg2 = (const float*)d_in[22];
    float* out = (float*)d_out;

    float *w1r, *w2r, *wdr;
    float *z1, *z2, *feat, *xw, *agg, *y1, *y2, *cs, *cd;
    float *alpha1, *beta1, *alpha2, *beta2, *betad;
    cudaGetSymbolAddress((void**)&w1r, g_w1r);
    cudaGetSymbolAddress((void**)&w2r, g_w2r);
    cudaGetSymbolAddress((void**)&wdr, g_wdr);
    cudaGetSymbolAddress((void**)&z1, g_z1);
    cudaGetSymbolAddress((void**)&z2, g_z2);
    cudaGetSymbolAddress((void**)&feat, g_feat);
    cudaGetSymbolAddress((void**)&xw, g_xw);
    cudaGetSymbolAddress((void**)&agg, g_agg);
    cudaGetSymbolAddress((void**)&y1, g_y1);
    cudaGetSymbolAddress((void**)&y2, g_y2);
    cudaGetSymbolAddress((void**)&cs, g_cs);
    cudaGetSymbolAddress((void**)&cd, g_cd);
    cudaGetSymbolAddress((void**)&alpha1, g_alpha1);
    cudaGetSymbolAddress((void**)&beta1, g_beta1);
    cudaGetSymbolAddress((void**)&alpha2, g_alpha2);
    cudaGetSymbolAddress((void**)&beta2, g_beta2);
    cudaGetSymbolAddress((void**)&betad, g_betad);

    cudaFuncSetAttribute(gemm_tc_kernel, cudaFuncAttributeMaxDynamicSharedMemorySize, SMEM_BYTES);

    prep_kernel<<<1, 512>>>(b1, g1, be1, m1, v1, b2, g2, be2, m2, v2, bd);

    // tf32 pre-rounding of weights only (h is rounded on-the-fly in the GEMM)
    {
        int n4 = 2 * DIN * H1 / 4;
        round_tf32_kernel<<<(n4 + 255) / 256, 256>>>(W1, w1r, n4);
        n4 = 2 * H1 * H2 / 4;
        round_tf32_kernel<<<(n4 + 255) / 256, 256>>>(W2, w2r, n4);
        n4 = 2 * H2 * DD / 4;
        round_tf32_kernel<<<(n4 + 255) / 256, 256>>>(Wd, wdr, n4);
    }

    zero_kernel<<<(NN + 255) / 256, 256>>>(cs, NN);
    zero_kernel<<<(NN + 255) / 256, 256>>>(cd, NN);
    deg_count_kernel<<<(NE + 255) / 256, 256>>>(src, dst);
    deg_finish_kernel<<<(NN + 255) / 256, 256>>>();

    // encoder layer 1: z1[m] = BN1(h[m] @ W1[m] + b1[m]); z1 tf32-rounded for enc2
    for (int m = 0; m < 2; m++) {
        gemm_tc_kernel<<<tc_grid(NN, H1), 128, SMEM_BYTES>>>(
            h + (size_t)m * NN * DIN, w1r + (size_t)m * DIN * H1,
            z1 + (size_t)m * NN * H1, NN, DIN, H1,
            alpha1 + m * H1, beta1 + m * H1, nullptr, 1.0f, 0, 0, 1);
    }

    // encoder layer 2: z2 tf32-rounded for dec
    for (int m = 0; m < 2; m++) {
        gemm_tc_kernel<<<tc_grid(NN, H2), 128, SMEM_BYTES>>>(
            z1 + (size_t)m * NN * H1, w2r + (size_t)m * H1 * H2,
            z2 + (size_t)m * NN * H2, NN, H1, H2,
            alpha2 + m * H2, beta2 + m * H2, nullptr, 1.0f, 0, 0, 1);
    }

    // decoder + modality mean (feat stays full fp32 for the SIMT graph GEMMs)
    gemm_tc_kernel<<<tc_grid(NN, DD), 128, SMEM_BYTES>>>(
        z2, wdr, feat, NN, H2, DD,
        nullptr, betad, nullptr, 0.5f, 0, 0, 0);
    gemm_tc_kernel<<<tc_grid(NN, DD), 128, SMEM_BYTES>>>(
        z2 + (size_t)NN * H2, wdr + (size_t)H2 * DD, feat, NN, H2, DD,
        nullptr, betad + DD, nullptr, 0.5f, 1, 0, 0);

    // ---- GraphConv 1: 64 -> 64, relu ----
    zero_kernel<<<(NN * DD + 255) / 256, 256>>>(agg, NN * DD);
    gemm64_kernel<<<gemm_grid(NN, DD), 256>>>(
        feat, Wg0, xw, NN, DD, DD, nullptr, nullptr, cs, 1.0f, 0, 0);
    scatter_kernel<<<(NE * 16 + 255) / 256, 256>>>(xw, agg, src, dst, 16);
    finalize_kernel<<<(NN * DD + 255) / 256, 256>>>(agg, y1, bg0, DD, 1);

    // ---- GraphConv 2: 64 -> 32, relu ----
    zero_kernel<<<(NN * 32 + 255) / 256, 256>>>(agg, NN * 32);
    gemm64_kernel<<<gemm_grid(NN, 32), 256>>>(
        y1, Wg1, xw, NN, DD, 32, nullptr, nullptr, cs, 1.0f, 0, 0);
    scatter_kernel<<<(NE * 8 + 255) / 256, 256>>>(xw, agg, src, dst, 8);
    finalize_kernel<<<(NN * 32 + 255) / 256, 256>>>(agg, y2, bg1, 32, 1);

    // ---- GraphConv 3: 32 -> 4, no relu, write output ----
    zero_kernel<<<(NN * 4 + 255) / 256, 256>>>(agg, NN * 4);
    gemm64_kernel<<<gemm_grid(NN, 4), 256>>>(
        y2, Wg2, xw, NN, 32, 4, nullptr, nullptr, cs, 1.0f, 0, 0);
    scatter_kernel<<<(NE * 1 + 255) / 256, 256>>>(xw, agg, src, dst, 1);
    finalize_kernel<<<(NN * 4 + 255) / 256, 256>>>(agg, out, bg2, 4, 0);
}